// round 1
// baseline (speedup 1.0000x reference)
#include <cuda_runtime.h>
#include <cuda_bf16.h>
#include <cstdint>

#define D_MODEL 1024
#define D_FF    4096
#define BATCH   4
#define SEQ     2048
#define MROWS   (BATCH * SEQ)   // 8192

// ---------------- scratch (static __device__, no allocations) ----------------
__device__ __nv_bfloat16 g_A[MROWS * D_MODEL];   // spikes in bf16    (16.8 MB)
__device__ __nv_bfloat16 g_W1[D_FF * D_MODEL];   // W1 in bf16        ( 8.4 MB)
__device__ __nv_bfloat16 g_H[(size_t)MROWS * D_FF]; // h = spikes@W1^T (67 MB)

// ---------------- fp32 -> bf16 converts ----------------
__global__ void cvtA_kernel(const float* __restrict__ src) {
    int i = blockIdx.x * blockDim.x + threadIdx.x;       // over float4 elems
    float4 v = reinterpret_cast<const float4*>(src)[i];
    __nv_bfloat162 lo = __floats2bfloat162_rn(v.x, v.y);
    __nv_bfloat162 hi = __floats2bfloat162_rn(v.z, v.w);
    reinterpret_cast<__nv_bfloat162*>(g_A)[i * 2 + 0] = lo;
    reinterpret_cast<__nv_bfloat162*>(g_A)[i * 2 + 1] = hi;
}

__global__ void cvtW1_kernel(const float* __restrict__ src) {
    int i = blockIdx.x * blockDim.x + threadIdx.x;
    float4 v = reinterpret_cast<const float4*>(src)[i];
    __nv_bfloat162 lo = __floats2bfloat162_rn(v.x, v.y);
    __nv_bfloat162 hi = __floats2bfloat162_rn(v.z, v.w);
    reinterpret_cast<__nv_bfloat162*>(g_W1)[i * 2 + 0] = lo;
    reinterpret_cast<__nv_bfloat162*>(g_W1)[i * 2 + 1] = hi;
}

// ---------------- zero the output ----------------
__global__ void zero_kernel(float4* __restrict__ out, int n4) {
    int i = blockIdx.x * blockDim.x + threadIdx.x;
    if (i < n4) out[i] = make_float4(0.f, 0.f, 0.f, 0.f);
}

// ---------------- GEMM: h[M,F] = A[M,D] @ W1[F,D]^T  (bf16 HMMA) ----------------
#define BM 128
#define BN 128
#define BK 32
#define KTILES (D_MODEL / BK)   // 32
#define SSTRIDE 40              // padded row stride (elements): 80B, 16B-aligned

__global__ __launch_bounds__(256) void gemm_h_kernel() {
    __shared__ __align__(16) __nv_bfloat16 As[2][BM][SSTRIDE];
    __shared__ __align__(16) __nv_bfloat16 Bs[2][BN][SSTRIDE];

    const int tid  = threadIdx.x;
    const int bm   = blockIdx.y * BM;   // gridDim.y = 64
    const int bn   = blockIdx.x * BN;   // gridDim.x = 32

    const int warp   = tid >> 5;
    const int lane   = tid & 31;
    const int wm     = warp >> 1;       // 0..3
    const int wn     = warp & 1;        // 0..1
    const int warp_m = wm * 32;
    const int warp_n = wn * 64;
    const int grp    = lane >> 2;       // 0..7
    const int q      = lane & 3;        // 0..3

    float acc[2][8][4];
    #pragma unroll
    for (int i = 0; i < 2; i++)
        #pragma unroll
        for (int j = 0; j < 8; j++)
            #pragma unroll
            for (int k = 0; k < 4; k++) acc[i][j][k] = 0.f;

    // stage loader: 512 16B chunks for A + 512 for B, 256 threads -> 2+2 each
    auto load_stage = [&](int buf, int kt) {
        const int k0 = kt * BK;
        #pragma unroll
        for (int i = 0; i < 2; i++) {
            int c   = tid + i * 256;
            int row = c >> 2;
            int kk  = (c & 3) * 8;
            const __nv_bfloat16* ga = &g_A[(size_t)(bm + row) * D_MODEL + k0 + kk];
            uint32_t sa = (uint32_t)__cvta_generic_to_shared(&As[buf][row][kk]);
            asm volatile("cp.async.ca.shared.global [%0], [%1], 16;\n"
                         :: "r"(sa), "l"(ga));
            const __nv_bfloat16* gb = &g_W1[(size_t)(bn + row) * D_MODEL + k0 + kk];
            uint32_t sb = (uint32_t)__cvta_generic_to_shared(&Bs[buf][row][kk]);
            asm volatile("cp.async.ca.shared.global [%0], [%1], 16;\n"
                         :: "r"(sb), "l"(gb));
        }
    };

    load_stage(0, 0);
    asm volatile("cp.async.commit_group;\n");

    for (int kt = 0; kt < KTILES; ++kt) {
        const int buf = kt & 1;
        if (kt + 1 < KTILES) {
            load_stage(buf ^ 1, kt + 1);
            asm volatile("cp.async.commit_group;\n");
            asm volatile("cp.async.wait_group 1;\n");
        } else {
            asm volatile("cp.async.wait_group 0;\n");
        }
        __syncthreads();

        #pragma unroll
        for (int ks = 0; ks < 2; ks++) {          // two k16 steps per BK=32
            const int kb = ks * 16;

            uint32_t a[2][4];
            #pragma unroll
            for (int fm = 0; fm < 2; fm++) {
                const __nv_bfloat16* p =
                    &As[buf][warp_m + fm * 16 + (lane & 15)][kb + ((lane >> 4) << 3)];
                uint32_t addr = (uint32_t)__cvta_generic_to_shared(p);
                asm volatile(
                    "ldmatrix.sync.aligned.m8n8.x4.shared.b16 {%0,%1,%2,%3}, [%4];\n"
                    : "=r"(a[fm][0]), "=r"(a[fm][1]), "=r"(a[fm][2]), "=r"(a[fm][3])
                    : "r"(addr));
            }

            uint32_t bf[4][4];
            #pragma unroll
            for (int fn2 = 0; fn2 < 4; fn2++) {
                int row = warp_n + fn2 * 16 + (lane & 7) + ((lane >> 4) << 3);
                int col = kb + (((lane >> 3) & 1) << 3);
                const __nv_bfloat16* p = &Bs[buf][row][col];
                uint32_t addr = (uint32_t)__cvta_generic_to_shared(p);
                asm volatile(
                    "ldmatrix.sync.aligned.m8n8.x4.shared.b16 {%0,%1,%2,%3}, [%4];\n"
                    : "=r"(bf[fn2][0]), "=r"(bf[fn2][1]), "=r"(bf[fn2][2]), "=r"(bf[fn2][3])
                    : "r"(addr));
            }

            #pragma unroll
            for (int fm = 0; fm < 2; fm++) {
                #pragma unroll
                for (int fn = 0; fn < 8; fn++) {
                    uint32_t b0 = bf[fn >> 1][(fn & 1) * 2 + 0];
                    uint32_t b1 = bf[fn >> 1][(fn & 1) * 2 + 1];
                    asm volatile(
                        "mma.sync.aligned.m16n8k16.row.col.f32.bf16.bf16.f32 "
                        "{%0,%1,%2,%3}, {%4,%5,%6,%7}, {%8,%9}, {%0,%1,%2,%3};\n"
                        : "+f"(acc[fm][fn][0]), "+f"(acc[fm][fn][1]),
                          "+f"(acc[fm][fn][2]), "+f"(acc[fm][fn][3])
                        : "r"(a[fm][0]), "r"(a[fm][1]), "r"(a[fm][2]), "r"(a[fm][3]),
                          "r"(b0), "r"(b1));
                }
            }
        }
        __syncthreads();
    }

    // epilogue: write h as bf16
    #pragma unroll
    for (int fm = 0; fm < 2; fm++) {
        #pragma unroll
        for (int fn = 0; fn < 8; fn++) {
            int r0 = bm + warp_m + fm * 16 + grp;
            int c  = bn + warp_n + fn * 8 + q * 2;
            __nv_bfloat162 v0 = __floats2bfloat162_rn(acc[fm][fn][0], acc[fm][fn][1]);
            __nv_bfloat162 v1 = __floats2bfloat162_rn(acc[fm][fn][2], acc[fm][fn][3]);
            *reinterpret_cast<__nv_bfloat162*>(&g_H[(size_t)r0 * D_FF + c])       = v0;
            *reinterpret_cast<__nv_bfloat162*>(&g_H[(size_t)(r0 + 8) * D_FF + c]) = v1;
        }
    }
}

// ---------------- rare-spike path: full-precision contribution ----------------
__device__ __noinline__ void sparse_emit(int b, int t, int f,
                                         const float* __restrict__ spikes,
                                         const float* __restrict__ Wr,
                                         const float* __restrict__ W2,
                                         float* __restrict__ out) {
    const float* x = spikes + ((size_t)b * SEQ + t) * D_MODEL;
    const float* w = Wr + (size_t)f * D_MODEL;
    float s = 0.f;
    for (int i = 0; i < D_MODEL; i++) s += x[i] * w[i];
    float r = 1.f / (1.f + expf(-s));
    float* o = out + ((size_t)b * SEQ + t) * D_MODEL;
    for (int d = 0; d < D_MODEL; d++)
        atomicAdd(&o[d], r * W2[(size_t)d * D_FF + f]);
}

// ---------------- EMA scan over T per (b,f) channel ----------------
__global__ void scan_kernel(const float* __restrict__ spikes,
                            const float* __restrict__ Wr,
                            const float* __restrict__ W2,
                            float* __restrict__ out) {
    int idx = blockIdx.x * blockDim.x + threadIdx.x;   // 16384 threads
    int b = idx >> 12;           // / D_FF
    int f = idx & (D_FF - 1);
    const __nv_bfloat16* hp = g_H + (size_t)b * SEQ * D_FF + f;

    float act = 0.f;
    for (int t0 = 0; t0 < SEQ; t0 += 32) {
        float hv[32];
        #pragma unroll
        for (int u = 0; u < 32; u++)
            hv[u] = __bfloat162float(hp[(size_t)(t0 + u) * D_FF]);
        #pragma unroll
        for (int u = 0; u < 32; u++) {
            act = 0.9f * act + 0.1f * hv[u];
            if (act > 0.5f)
                sparse_emit(b, t0 + u, f, spikes, Wr, W2, out);
        }
    }
}

// ---------------- entry ----------------
extern "C" void kernel_launch(void* const* d_in, const int* in_sizes, int n_in,
                              void* d_out, int out_size) {
    const float* spikes = (const float*)d_in[0];   // [B,T,D]
    const float* W1     = (const float*)d_in[1];   // [F,D]   (unused beyond convert)
    const float* W2     = (const float*)d_in[2];   // [D,F]
    const float* Wr     = (const float*)d_in[3];   // [F,D]
    float* out = (float*)d_out;

    (void)in_sizes; (void)n_in;

    // 1) converts
    cvtA_kernel<<<(MROWS * D_MODEL / 4) / 256, 256>>>(spikes);
    cvtW1_kernel<<<(D_FF * D_MODEL / 4) / 256, 256>>>(W1);

    // 2) GEMM h = spikes @ W1^T
    dim3 grid(D_FF / BN, MROWS / BM);   // (32, 64)
    gemm_h_kernel<<<grid, 256>>>();

    // 3) zero output
    int n4 = out_size / 4;
    zero_kernel<<<(n4 + 255) / 256, 256>>>((float4*)out, n4);

    // 4) EMA scan + rare-spike sparse emission
    scan_kernel<<<128, 128>>>(spikes, Wr, W2, out);
}

// round 5
// speedup vs baseline: 1.3951x; 1.3951x over previous
#include <cuda_runtime.h>
#include <cuda_bf16.h>
#include <cstdint>

#define D_MODEL 1024
#define D_FF    4096
#define BATCH   4
#define SEQ     2048
#define MROWS   (BATCH * SEQ)   // 8192
#define MAXF    1024
#define FLAG_THRESH 0.45f

// ---------------- scratch (static __device__, no allocations) ----------------
__device__ __nv_bfloat16 g_X[MROWS * D_MODEL];   // xema in bf16 (16.8 MB)
__device__ __nv_bfloat16 g_W1[D_FF * D_MODEL];   // W1 in bf16   ( 8.4 MB)
__device__ int      g_nflag;
__device__ uint32_t g_flags[MAXF];               // packed m*4096+f

// ---------------- fp32 -> bf16 convert for W1 ----------------
__global__ void cvtW1_kernel(const float* __restrict__ src) {
    int i = blockIdx.x * blockDim.x + threadIdx.x;
    float4 v = reinterpret_cast<const float4*>(src)[i];
    reinterpret_cast<__nv_bfloat162*>(g_W1)[i * 2 + 0] = __floats2bfloat162_rn(v.x, v.y);
    reinterpret_cast<__nv_bfloat162*>(g_W1)[i * 2 + 1] = __floats2bfloat162_rn(v.z, v.w);
}

// ---------------- EMA over time in input space: xema = EMA_t(spikes) --------
// Chunked scan: chunk=128 steps, warm-up=128 steps (0.9^128 = 1.4e-6 -> exact
// to ~1e-7 absolute, margin to threshold is 0.05).
#define CH 128
__global__ void ema_kernel(const float* __restrict__ spikes) {
    int idx = blockIdx.x * blockDim.x + threadIdx.x;   // 65536 threads
    if (idx == 0) g_nflag = 0;                         // reset flag count
    int d = idx & (D_MODEL - 1);
    int c = (idx >> 10) & 15;                          // chunk id (T/CH = 16)
    int b = idx >> 14;
    const float* x = spikes + (size_t)b * SEQ * D_MODEL + d;
    int t0 = c * CH;
    int start = t0 - CH; if (start < 0) start = 0;

    float act = 0.f;
    #pragma unroll 8
    for (int t = start; t < t0; t++)
        act = fmaf(0.9f, act, 0.1f * x[(size_t)t * D_MODEL]);

    __nv_bfloat16* o = g_X + ((size_t)b * SEQ + t0) * D_MODEL + d;
    #pragma unroll 8
    for (int t = 0; t < CH; t++) {
        act = fmaf(0.9f, act, 0.1f * x[(size_t)(t0 + t) * D_MODEL]);
        o[(size_t)t * D_MODEL] = __float2bfloat16(act);
    }
}

// ---------------- zero the output (+ nothing else) ----------------
__global__ void zero_kernel(float4* __restrict__ out, int n4) {
    int i = blockIdx.x * blockDim.x + threadIdx.x;
    if (i < n4) out[i] = make_float4(0.f, 0.f, 0.f, 0.f);
}

// ========== GEMM: mixed[M,F] = xema[M,D] @ W1[F,D]^T ; epilogue = flag check =====
// BM=128, BN=256, BK=32, 256 threads (8 warps, each 64x64), 4-stage cp.async.
#define BM 128
#define BN 256
#define BK 32
#define KTILES (D_MODEL / BK)        // 32
#define SROWB 80                     // padded row: 40 bf16 = 80B
#define STAGE_A (BM * SROWB)         // 10240
#define STAGE_B (BN * SROWB)         // 20480
#define STAGE_BYTES (STAGE_A + STAGE_B)
#define GEMM_SMEM (4 * STAGE_BYTES)  // 122880

__device__ __forceinline__ void cp_async16(uint32_t dst, const void* src) {
    asm volatile("cp.async.cg.shared.global [%0], [%1], 16;\n" :: "r"(dst), "l"(src));
}

__global__ void __launch_bounds__(256, 1) gemm_kernel() {
    extern __shared__ char dyn_smem[];
    const uint32_t smem0 = (uint32_t)__cvta_generic_to_shared(dyn_smem);

    const int tid  = threadIdx.x;
    const int bm   = blockIdx.y * BM;   // 64 tiles
    const int bn   = blockIdx.x * BN;   // 16 tiles
    const int warp = tid >> 5;
    const int lane = tid & 31;
    const int warp_m = (warp & 1) * 64;
    const int warp_n = (warp >> 1) * 64;
    const int grp = lane >> 2;
    const int q   = lane & 3;

    const __nv_bfloat16* gA = g_X  + (size_t)bm * D_MODEL;
    const __nv_bfloat16* gB = g_W1 + (size_t)bn * D_MODEL;

    float acc[4][8][4];
    #pragma unroll
    for (int i = 0; i < 4; i++)
        #pragma unroll
        for (int j = 0; j < 8; j++)
            #pragma unroll
            for (int k = 0; k < 4; k++) acc[i][j][k] = 0.f;

    auto load_stage = [&](int kt) {
        const int s = kt & 3;
        const int k0 = kt * BK;
        const uint32_t baseA = smem0 + s * STAGE_BYTES;
        const uint32_t baseB = baseA + STAGE_A;
        #pragma unroll
        for (int i = 0; i < 2; i++) {               // A: 512 chunks of 16B
            int c = tid + i * 256;
            int row = c >> 2, kk = (c & 3) * 8;
            cp_async16(baseA + row * SROWB + kk * 2,
                       gA + (size_t)row * D_MODEL + k0 + kk);
        }
        #pragma unroll
        for (int i = 0; i < 4; i++) {               // B: 1024 chunks of 16B
            int c = tid + i * 256;
            int row = c >> 2, kk = (c & 3) * 8;
            cp_async16(baseB + row * SROWB + kk * 2,
                       gB + (size_t)row * D_MODEL + k0 + kk);
        }
    };

    #pragma unroll
    for (int p = 0; p < 3; p++) {
        load_stage(p);
        asm volatile("cp.async.commit_group;\n" ::: "memory");
    }

    for (int kt = 0; kt < KTILES; kt++) {
        const int s = kt & 3;
        asm volatile("cp.async.wait_group 2;\n" ::: "memory");
        __syncthreads();

        const uint32_t baseA = smem0 + s * STAGE_BYTES;
        const uint32_t baseB = baseA + STAGE_A;

        #pragma unroll
        for (int ks = 0; ks < 2; ks++) {
            const int kb = ks * 16;
            uint32_t a[4][4];
            #pragma unroll
            for (int fm = 0; fm < 4; fm++) {
                int row = warp_m + fm * 16 + (lane & 15);
                int col = kb + ((lane >> 4) << 3);
                uint32_t addr = baseA + row * SROWB + col * 2;
                asm volatile(
                    "ldmatrix.sync.aligned.m8n8.x4.shared.b16 {%0,%1,%2,%3}, [%4];\n"
                    : "=r"(a[fm][0]), "=r"(a[fm][1]), "=r"(a[fm][2]), "=r"(a[fm][3])
                    : "r"(addr));
            }
            uint32_t bf[4][4];
            #pragma unroll
            for (int fn2 = 0; fn2 < 4; fn2++) {
                int row = warp_n + fn2 * 16 + (lane & 7) + ((lane >> 4) << 3);
                int col = kb + (((lane >> 3) & 1) << 3);
                uint32_t addr = baseB + row * SROWB + col * 2;
                asm volatile(
                    "ldmatrix.sync.aligned.m8n8.x4.shared.b16 {%0,%1,%2,%3}, [%4];\n"
                    : "=r"(bf[fn2][0]), "=r"(bf[fn2][1]), "=r"(bf[fn2][2]), "=r"(bf[fn2][3])
                    : "r"(addr));
            }
            #pragma unroll
            for (int fm = 0; fm < 4; fm++) {
                #pragma unroll
                for (int fn = 0; fn < 8; fn++) {
                    uint32_t b0 = bf[fn >> 1][(fn & 1) * 2 + 0];
                    uint32_t b1 = bf[fn >> 1][(fn & 1) * 2 + 1];
                    asm volatile(
                        "mma.sync.aligned.m16n8k16.row.col.f32.bf16.bf16.f32 "
                        "{%0,%1,%2,%3}, {%4,%5,%6,%7}, {%8,%9}, {%0,%1,%2,%3};\n"
                        : "+f"(acc[fm][fn][0]), "+f"(acc[fm][fn][1]),
                          "+f"(acc[fm][fn][2]), "+f"(acc[fm][fn][3])
                        : "r"(a[fm][0]), "r"(a[fm][1]), "r"(a[fm][2]), "r"(a[fm][3]),
                          "r"(b0), "r"(b1));
                }
            }
        }

        const int fill = kt + 3;
        if (fill < KTILES) load_stage(fill);
        asm volatile("cp.async.commit_group;\n" ::: "memory");
    }

    // epilogue: flag any mixed > FLAG_THRESH (true spikes need > 0.5; ~140 sigma margin)
    #pragma unroll
    for (int fm = 0; fm < 4; fm++) {
        #pragma unroll
        for (int fn = 0; fn < 8; fn++) {
            #pragma unroll
            for (int e = 0; e < 4; e++) {
                if (acc[fm][fn][e] > FLAG_THRESH) {
                    int m = bm + warp_m + fm * 16 + grp + ((e >> 1) ? 8 : 0);
                    int f = bn + warp_n + fn * 8 + q * 2 + (e & 1);
                    int idx = atomicAdd(&g_nflag, 1);
                    if (idx < MAXF) g_flags[idx] = (uint32_t)(m * D_FF + f);
                }
            }
        }
    }
}

// ---------------- exact fixup for flagged (m,f): full fp32 recompute ----------
__global__ void fixup_kernel(const float* __restrict__ spikes,
                             const float* __restrict__ W1,
                             const float* __restrict__ Wr,
                             const float* __restrict__ W2,
                             float* __restrict__ out) {
    int n = g_nflag; if (n > MAXF) n = MAXF;
    if (n == 0) return;
    int warp = threadIdx.x >> 5, lane = threadIdx.x & 31;
    for (int e = blockIdx.x * (blockDim.x >> 5) + warp; e < n;
         e += gridDim.x * (blockDim.x >> 5)) {
        uint32_t p = g_flags[e];
        int f = (int)(p & (D_FF - 1));
        int m = (int)(p / D_FF);
        int b = m >> 11, t = m & (SEQ - 1);
        const float* X  = spikes + (size_t)b * SEQ * D_MODEL;
        const float* w1 = W1 + (size_t)f * D_MODEL;
        float mixed = 0.f;
        for (int s = 0; s <= t; s++) {
            const float* x = X + (size_t)s * D_MODEL;
            float part = 0.f;
            for (int d = lane; d < D_MODEL; d += 32) part += x[d] * w1[d];
            #pragma unroll
            for (int o = 16; o; o >>= 1) part += __shfl_xor_sync(~0u, part, o);
            mixed = 0.9f * mixed + 0.1f * part;
        }
        if (mixed > 0.5f) {
            const float* wr = Wr + (size_t)f * D_MODEL;
            const float* x  = X + (size_t)t * D_MODEL;
            float sr = 0.f;
            for (int d = lane; d < D_MODEL; d += 32) sr += x[d] * wr[d];
            #pragma unroll
            for (int o = 16; o; o >>= 1) sr += __shfl_xor_sync(~0u, sr, o);
            float r = 1.f / (1.f + expf(-sr));
            float* o_ = out + ((size_t)b * SEQ + t) * D_MODEL;
            for (int d = lane; d < D_MODEL; d += 32)
                atomicAdd(&o_[d], r * W2[(size_t)d * D_FF + f]);
        }
    }
}

// ---------------- entry ----------------
extern "C" void kernel_launch(void* const* d_in, const int* in_sizes, int n_in,
                              void* d_out, int out_size) {
    const float* spikes = (const float*)d_in[0];   // [B,T,D]
    const float* W1     = (const float*)d_in[1];   // [F,D]
    const float* W2     = (const float*)d_in[2];   // [D,F]
    const float* Wr     = (const float*)d_in[3];   // [F,D]
    float* out = (float*)d_out;
    (void)in_sizes; (void)n_in;

    cvtW1_kernel<<<(D_FF * D_MODEL / 4) / 256, 256>>>(W1);
    ema_kernel<<<(BATCH * 16 * D_MODEL) / 256, 256>>>(spikes);   // also resets g_nflag

    cudaFuncSetAttribute(gemm_kernel, cudaFuncAttributeMaxDynamicSharedMemorySize, GEMM_SMEM);
    dim3 grid(D_FF / BN, MROWS / BM);   // (16, 64)
    gemm_kernel<<<grid, 256, GEMM_SMEM>>>();

    int n4 = out_size / 4;
    zero_kernel<<<(n4 + 255) / 256, 256>>>((float4*)out, n4);

    fixup_kernel<<<32, 256>>>(spikes, W1, Wr, W2, out);
}